// round 12
// baseline (speedup 1.0000x reference)
#include <cuda_runtime.h>
#include <cstdint>

// Problem constants
#define S_    8
#define U_    8
#define K_    12
#define NEG_  17
#define ZD    64
#define CD    256
#define T_    1140
#define LEN   1128
#define SU    64
#define TOTPOS 72192

#define NCTA 288
#define TILES_PER_CTA 24        // 288*24 = 6912 = 12 k * 9 ltiles * 64 su

__device__ double g_loss[K_];
__device__ double g_acc[K_];

__global__ void zero_accum() {
    int i = threadIdx.x;
    if (i < K_) { g_loss[i] = 0.0; g_acc[i] = 0.0; }
}

// ---------------- smem layout (float offsets) ----------------
#define ASB 132                       // A stride (128 rows + pad)
#define BSB 68                        // B/wc stride (64 cols + pad)
#define OFF_AS 0                      // As[16][132]
#define OFF_BS (16 * ASB)             // Bs[16][68]
#define OFF_WC (OFF_BS + 16 * BSB)    // wc[2][128][68]
#define WC_BUF (128 * BSB)
#define OFF_SL (OFF_WC + 2 * WC_BUF)
#define OFF_SA (OFF_SL + 12)
#define SMEM_FLOATS (OFF_SA + 12 + 4)
#define SMEM_BYTES (SMEM_FLOATS * 4)  // ~83 KB -> 2 CTAs/SM

// tile id -> (k, l0, su); k fastest so a CTA reuses its c-chunk 12x via L2
__device__ __forceinline__ void tile_coords(int t, int& k, int& l0, int& su) {
    k = t % 12;
    int rs = t / 12;
    l0 = (rs % 9) * 128;
    su = rs / 9;
}

// ---------------- GEMM phase: wc[128 l x 64 z] = c-chunk @ W[k]^T + b[k] ----------------
__device__ __forceinline__ void tile_gemm(
    const float* __restrict__ C, const float* __restrict__ W,
    const float* __restrict__ Bias, float* As, float* Bs, float* wc,
    int k, int l0, int su, int tid)
{
    const int ty = tid >> 3;          // 0..31 -> rows ty*4..+4
    const int tx = tid & 7;           // 0..7  -> cols tx*8..+8

    float acc[4][8];
#pragma unroll
    for (int i = 0; i < 4; i++)
#pragma unroll
        for (int j = 0; j < 8; j++) acc[i][j] = 0.0f;

    for (int kt = 0; kt < CD; kt += 16) {
        // A tile: 128 rows x 16 cols = 512 float4, 2/thread
#pragma unroll
        for (int r = 0; r < 2; r++) {
            int f = r * 256 + tid;
            int row = f >> 2, c4 = f & 3;
            int rr = l0 + row; if (rr > T_ - 1) rr = T_ - 1;   // clamp; junk rows unused
            const float4 v = *(const float4*)(C + ((size_t)su * T_ + rr) * CD + kt + c4 * 4);
            As[(c4 * 4 + 0) * ASB + row] = v.x;
            As[(c4 * 4 + 1) * ASB + row] = v.y;
            As[(c4 * 4 + 2) * ASB + row] = v.z;
            As[(c4 * 4 + 3) * ASB + row] = v.w;
        }
        // B tile: 64 x 16 = 256 float4, 1/thread
        {
            int n = tid >> 2, c4 = tid & 3;
            const float4 v = *(const float4*)(W + ((size_t)k * ZD + n) * CD + kt + c4 * 4);
            Bs[(c4 * 4 + 0) * BSB + n] = v.x;
            Bs[(c4 * 4 + 1) * BSB + n] = v.y;
            Bs[(c4 * 4 + 2) * BSB + n] = v.z;
            Bs[(c4 * 4 + 3) * BSB + n] = v.w;
        }
        __syncthreads();
#pragma unroll
        for (int kk = 0; kk < 16; kk++) {
            float4 av = *(const float4*)&As[kk * ASB + ty * 4];
            float4 b0 = *(const float4*)&Bs[kk * BSB + tx * 8];
            float4 b1 = *(const float4*)&Bs[kk * BSB + tx * 8 + 4];
            float a[4] = {av.x, av.y, av.z, av.w};
            float b[8] = {b0.x, b0.y, b0.z, b0.w, b1.x, b1.y, b1.z, b1.w};
#pragma unroll
            for (int i = 0; i < 4; i++)
#pragma unroll
                for (int j = 0; j < 8; j++) acc[i][j] += a[i] * b[j];
        }
        __syncthreads();
    }

    float bias[8];
#pragma unroll
    for (int j = 0; j < 8; j++) bias[j] = __ldg(Bias + k * ZD + tx * 8 + j);
#pragma unroll
    for (int i = 0; i < 4; i++) {
        int row = ty * 4 + i;
#pragma unroll
        for (int j = 0; j < 8; j++)
            wc[row * BSB + tx * 8 + j] = acc[i][j] + bias[j];
    }
}

// ---------------- loss phase: 128 l's of one (k, su) from smem wc ----------------
__device__ __forceinline__ void tile_loss(
    const float* __restrict__ z, const int* __restrict__ batch_index,
    const int* __restrict__ seq_index, const float* wc,
    float* sLoss, float* sAcc, int k, int l0, int su, int tid)
{
    const int lane = tid & 31;
    const int g8   = tid >> 3;
    const int lg   = tid & 7;
    const unsigned gmask = 0xFFu << ((lane >> 3) * 8);
    const int s = su >> 3, u = su & 7;
    const int kshift = k + 1;

    float lt = 0.f, oka = 0.f;

#pragma unroll 1
    for (int j = 0; j < 4; j++) {
        const int lrow = g8 * 4 + j;
        const int l = l0 + lrow;
        if (l < LEN) {
            const float* wrow = wc + lrow * BSB;
            const float4 wa = *(const float4*)(wrow + 4 * lg);
            const float4 wb = *(const float4*)(wrow + 32 + 4 * lg);

            const float* zp = z + ((size_t)(su * T_ + l + kshift)) * ZD;
            float4 za = *(const float4*)(zp + 4 * lg);
            float4 zb = *(const float4*)(zp + 32 + 4 * lg);
            float v = wa.x * za.x + wa.y * za.y + wa.z * za.z + wa.w * za.w
                    + wb.x * zb.x + wb.y * zb.y + wb.z * zb.z + wb.w * zb.w;
            v += __shfl_xor_sync(gmask, v, 1);
            v += __shfl_xor_sync(gmask, v, 2);
            v += __shfl_xor_sync(gmask, v, 4);
            const float pos = v * 0.125f;

            const int* bip = batch_index + (k * U_ + u) * NEG_;
            const int* sip = seq_index + ((size_t)((k * S_ + s) * U_ + u) * NEG_) * LEN + l;
            int bis[NEG_], sis[NEG_];
#pragma unroll
            for (int n = 0; n < NEG_; n++) {
                bis[n] = __ldg(bip + n);
                sis[n] = __ldg(sip + (size_t)n * LEN);
            }

            float m = pos, ssum = 1.0f, ok = 1.0f;
#pragma unroll
            for (int n = 0; n < NEG_; n++) {
                const float* zr = z + ((size_t)((s * 8 + bis[n]) * T_ + sis[n] + kshift)) * ZD;
                float4 na = *(const float4*)(zr + 4 * lg);
                float4 nb = *(const float4*)(zr + 32 + 4 * lg);
                float d = wa.x * na.x + wa.y * na.y + wa.z * na.z + wa.w * na.w
                        + wb.x * nb.x + wb.y * nb.y + wb.z * nb.z + wb.w * nb.w;
                d += __shfl_xor_sync(gmask, d, 1);
                d += __shfl_xor_sync(gmask, d, 2);
                d += __shfl_xor_sync(gmask, d, 4);
                d *= 0.125f;
                if (d > pos) ok = 0.0f;
                if (d > m) { ssum = ssum * __expf(m - d) + 1.0f; m = d; }
                else       { ssum += __expf(d - m); }
            }
            lt  += m + __logf(ssum) - pos;
            oka += ok;
        }
    }

    // cross-group warp reduce (uniform within each 8-lane group)
    lt  += __shfl_xor_sync(0xffffffffu, lt, 8);
    lt  += __shfl_xor_sync(0xffffffffu, lt, 16);
    oka += __shfl_xor_sync(0xffffffffu, oka, 8);
    oka += __shfl_xor_sync(0xffffffffu, oka, 16);
    if (lane == 0) {
        atomicAdd(&sLoss[k], lt);
        atomicAdd(&sAcc[k],  oka);
    }
}

// ================= anti-phased persistent fused kernel =================
// Even CTAs: G(i); L(i). Odd CTAs: G(0); G(1); then L(i); G(i+2) — one full
// GEMM phase ahead of the even CTA sharing the SM, so FMA-bound and L2-bound
// phases overlap across the two independent CTAs. Only __syncthreads().
__global__ __launch_bounds__(256, 2) void fused_ap(
    const float* __restrict__ C,
    const float* __restrict__ W,
    const float* __restrict__ Bias,
    const float* __restrict__ z,
    const int* __restrict__ batch_index,
    const int* __restrict__ seq_index)
{
    extern __shared__ float smf[];
    float* As    = smf + OFF_AS;
    float* Bs    = smf + OFF_BS;
    float* sLoss = smf + OFF_SL;
    float* sAcc  = smf + OFF_SA;

    const int tid  = threadIdx.x;
    const int base = blockIdx.x * TILES_PER_CTA;
    if (tid < 12) { sLoss[tid] = 0.0f; sAcc[tid] = 0.0f; }
    __syncthreads();

    int k, l0, su;

    if (!(blockIdx.x & 1)) {
        // -------- even CTA: G(i); L(i) --------
        for (int i = 0; i < TILES_PER_CTA; i++) {
            float* wc = smf + OFF_WC + (i & 1) * WC_BUF;
            tile_coords(base + i, k, l0, su);
            tile_gemm(C, W, Bias, As, Bs, wc, k, l0, su, tid);
            __syncthreads();
            tile_loss(z, batch_index, seq_index, wc, sLoss, sAcc, k, l0, su, tid);
            __syncthreads();
        }
    } else {
        // -------- odd CTA: G(0); G(1); { L(i); G(i+2) }; L(22); L(23) --------
        tile_coords(base + 0, k, l0, su);
        tile_gemm(C, W, Bias, As, Bs, smf + OFF_WC, k, l0, su, tid);
        __syncthreads();
        tile_coords(base + 1, k, l0, su);
        tile_gemm(C, W, Bias, As, Bs, smf + OFF_WC + WC_BUF, k, l0, su, tid);
        __syncthreads();
        for (int i = 0; i < TILES_PER_CTA - 2; i++) {
            float* wc = smf + OFF_WC + (i & 1) * WC_BUF;
            tile_coords(base + i, k, l0, su);
            tile_loss(z, batch_index, seq_index, wc, sLoss, sAcc, k, l0, su, tid);
            __syncthreads();
            tile_coords(base + i + 2, k, l0, su);
            tile_gemm(C, W, Bias, As, Bs, wc, k, l0, su, tid);   // same buf: (i+2)&1 == i&1
            __syncthreads();
        }
        for (int i = TILES_PER_CTA - 2; i < TILES_PER_CTA; i++) {
            float* wc = smf + OFF_WC + (i & 1) * WC_BUF;
            tile_coords(base + i, k, l0, su);
            tile_loss(z, batch_index, seq_index, wc, sLoss, sAcc, k, l0, su, tid);
            __syncthreads();
        }
    }

    if (tid < 12) {
        atomicAdd(&g_loss[tid], (double)sLoss[tid]);
        atomicAdd(&g_acc[tid],  (double)sAcc[tid]);
    }
}

// ================= finalize =================
__global__ void finalize(float* __restrict__ out, int out_size) {
    if (threadIdx.x == 0) {
        double tot = 0.0;
#pragma unroll
        for (int kk = 0; kk < K_; kk++) tot += g_loss[kk];
        if (out_size > 0) out[0] = (float)(tot / ((double)K_ * (double)TOTPOS));
#pragma unroll
        for (int kk = 0; kk < K_; kk++)
            if (1 + kk < out_size) out[1 + kk] = (float)(g_acc[kk] / (double)TOTPOS);
    }
}

// ---------------- launch ----------------
extern "C" void kernel_launch(void* const* d_in, const int* in_sizes, int n_in,
                              void* d_out, int out_size) {
    const float* z  = (const float*)d_in[0];
    const float* c  = (const float*)d_in[1];
    const float* W  = (const float*)d_in[2];
    const float* b  = (const float*)d_in[3];
    const int* bidx = (const int*)d_in[4];
    const int* sidx = (const int*)d_in[5];

    cudaFuncSetAttribute(fused_ap, cudaFuncAttributeMaxDynamicSharedMemorySize, SMEM_BYTES);

    zero_accum<<<1, 32>>>();

    fused_ap<<<NCTA, 256, SMEM_BYTES>>>(c, W, b, z, bidx, sidx);

    finalize<<<1, 32>>>((float*)d_out, out_size);
}

// round 13
// speedup vs baseline: 1.1222x; 1.1222x over previous
#include <cuda_runtime.h>
#include <cstdint>

// Problem constants
#define S_    8
#define U_    8
#define K_    12
#define NEG_  17
#define ZD    64
#define CD    256
#define T_    1140
#define LEN   1128
#define SU    64
#define TOTPOS 72192

// ---------------- scratch ----------------
__device__ float  g_Wc[(size_t)K_ * TOTPOS * ZD];   // ~222 MB
__device__ double g_loss[K_];
__device__ double g_acc[K_];

__global__ void zero_accum() {
    int i = threadIdx.x;
    if (i < K_) { g_loss[i] = 0.0; g_acc[i] = 0.0; }
}

// ================= GEMM for one k (R2-proven body) =================
// Wc[k][su][l][:] = c[su][l][:] @ W[k][:][:]^T + b[k][:]
#define BM 128
#define BN 64
#define BK 16

__global__ __launch_bounds__(256) void gemm_k(const float* __restrict__ C,
                                              const float* __restrict__ W,
                                              const float* __restrict__ Bias,
                                              int k) {
    __shared__ float As[BK][BM + 4];
    __shared__ float Bs[BK][BN + 4];

    const int lt = blockIdx.x;   // 0..8
    const int su = blockIdx.y;   // 0..63
    const int l0 = lt * BM;
    const int tid = threadIdx.x;
    const int tx = tid & 15;     // n / 4
    const int ty = tid >> 4;     // m / 8

    const float* Ag = C + ((size_t)su * T_ + l0) * CD;
    const float* Bg = W + (size_t)k * ZD * CD;

    float acc[8][4];
#pragma unroll
    for (int i = 0; i < 8; i++)
#pragma unroll
        for (int j = 0; j < 4; j++) acc[i][j] = 0.0f;

    for (int kt = 0; kt < CD; kt += BK) {
        // A tile: 128 rows x 16 cols = 512 float4; 2 per thread
#pragma unroll
        for (int r = 0; r < 2; ++r) {
            int f   = r * 256 + tid;
            int row = f >> 2;
            int c4  = f & 3;
            float4 v = make_float4(0.f, 0.f, 0.f, 0.f);
            if (l0 + row < LEN)
                v = *(const float4*)(Ag + (size_t)row * CD + kt + c4 * 4);
            As[c4 * 4 + 0][row] = v.x;
            As[c4 * 4 + 1][row] = v.y;
            As[c4 * 4 + 2][row] = v.z;
            As[c4 * 4 + 3][row] = v.w;
        }
        // B tile: 64 rows x 16 cols = 256 float4; 1 per thread
        {
            int n  = tid >> 2;
            int c4 = tid & 3;
            float4 v = *(const float4*)(Bg + (size_t)n * CD + kt + c4 * 4);
            Bs[c4 * 4 + 0][n] = v.x;
            Bs[c4 * 4 + 1][n] = v.y;
            Bs[c4 * 4 + 2][n] = v.z;
            Bs[c4 * 4 + 3][n] = v.w;
        }
        __syncthreads();

#pragma unroll
        for (int kk = 0; kk < BK; ++kk) {
            float4 a0 = *(const float4*)&As[kk][ty * 8 + 0];
            float4 a1 = *(const float4*)&As[kk][ty * 8 + 4];
            float4 bv = *(const float4*)&Bs[kk][tx * 4];
            float a[8] = {a0.x, a0.y, a0.z, a0.w, a1.x, a1.y, a1.z, a1.w};
            float b[4] = {bv.x, bv.y, bv.z, bv.w};
#pragma unroll
            for (int i = 0; i < 8; i++)
#pragma unroll
                for (int j = 0; j < 4; j++) acc[i][j] += a[i] * b[j];
        }
        __syncthreads();
    }

    const float4 bias = *(const float4*)(Bias + k * ZD + tx * 4);
    float* outp = g_Wc + ((size_t)k * TOTPOS + (size_t)su * LEN) * ZD;
#pragma unroll
    for (int i = 0; i < 8; i++) {
        int l = l0 + ty * 8 + i;
        if (l < LEN) {
            float4 o;
            o.x = acc[i][0] + bias.x;
            o.y = acc[i][1] + bias.y;
            o.z = acc[i][2] + bias.z;
            o.w = acc[i][3] + bias.w;
            *(float4*)(outp + (size_t)l * ZD + tx * 4) = o;
        }
    }
}

// ================= CPC loss for one k (R2-proven body + PDL trigger) =================
#define BLOCKS_PER_K 2256   // 18048 warps / 8 per block

__global__ __launch_bounds__(256) void loss_k(const float* __restrict__ z,
                                              const int* __restrict__ batch_index,
                                              const int* __restrict__ seq_index,
                                              int k) {
    // PDL: release the dependent (next gemm_k) immediately — it has no data
    // dependence on this kernel, so it can fill the SMs alongside us.
    asm volatile("griddepcontrol.launch_dependents;" ::: "memory");

    const int wid  = threadIdx.x >> 5;
    const int lane = threadIdx.x & 31;
    const int grp  = lane >> 3;
    const int lg   = lane & 7;

    const int wg  = blockIdx.x * 8 + wid;   // 0..18047 within this k
    const int su  = wg / 282;
    const int l   = (wg % 282) * 4 + grp;   // 282*4 == 1128, always in range
    const int s   = su >> 3;
    const int u   = su & 7;
    const int kshift = k + 1;

    const float* wc = g_Wc + ((size_t)k * TOTPOS + (size_t)su * LEN + l) * ZD;
    const float4 wa = *(const float4*)(wc + 4 * lg);
    const float4 wb = *(const float4*)(wc + 32 + 4 * lg);

    const float* zp = z + ((size_t)(su * T_ + l + kshift)) * ZD;
    float4 za = *(const float4*)(zp + 4 * lg);
    float4 zb = *(const float4*)(zp + 32 + 4 * lg);
    float v = wa.x * za.x + wa.y * za.y + wa.z * za.z + wa.w * za.w
            + wb.x * zb.x + wb.y * zb.y + wb.z * zb.z + wb.w * zb.w;
    v += __shfl_xor_sync(0xffffffffu, v, 1);
    v += __shfl_xor_sync(0xffffffffu, v, 2);
    v += __shfl_xor_sync(0xffffffffu, v, 4);
    const float pos = v * 0.125f;

    const int* bip = batch_index + (k * U_ + u) * NEG_;
    const int* sip = seq_index + ((size_t)((k * S_ + s) * U_ + u) * NEG_) * LEN + l;
    int bis[NEG_], sis[NEG_];
#pragma unroll
    for (int n = 0; n < NEG_; n++) {
        bis[n] = __ldg(bip + n);
        sis[n] = __ldg(sip + (size_t)n * LEN);
    }

    float m = pos, ssum = 1.0f, ok = 1.0f;
#pragma unroll
    for (int n = 0; n < NEG_; n++) {
        const float* zr = z + ((size_t)((s * 8 + bis[n]) * T_ + sis[n] + kshift)) * ZD;
        float4 na = *(const float4*)(zr + 4 * lg);
        float4 nb = *(const float4*)(zr + 32 + 4 * lg);
        float d = wa.x * na.x + wa.y * na.y + wa.z * na.z + wa.w * na.w
                + wb.x * nb.x + wb.y * nb.y + wb.z * nb.z + wb.w * nb.w;
        d += __shfl_xor_sync(0xffffffffu, d, 1);
        d += __shfl_xor_sync(0xffffffffu, d, 2);
        d += __shfl_xor_sync(0xffffffffu, d, 4);
        d *= 0.125f;
        if (d > pos) ok = 0.0f;                 // argmax==0 iff pos >= every neg
        if (d > m) { ssum = ssum * __expf(m - d) + 1.0f; m = d; }
        else       { ssum += __expf(d - m); }
    }

    float lt = m + __logf(ssum) - pos;          // log_z - f0

    lt += __shfl_xor_sync(0xffffffffu, lt, 8);
    lt += __shfl_xor_sync(0xffffffffu, lt, 16);
    ok += __shfl_xor_sync(0xffffffffu, ok, 8);
    ok += __shfl_xor_sync(0xffffffffu, ok, 16);

    __shared__ float sL[8], sA[8];
    if (lane == 0) { sL[wid] = lt; sA[wid] = ok; }
    __syncthreads();
    if (threadIdx.x == 0) {
        float L = 0.f, A = 0.f;
#pragma unroll
        for (int i = 0; i < 8; i++) { L += sL[i]; A += sA[i]; }
        atomicAdd(&g_loss[k], (double)L);
        atomicAdd(&g_acc[k], (double)A);
    }
}

// ================= finalize =================
__global__ void finalize(float* __restrict__ out, int out_size) {
    if (threadIdx.x == 0) {
        double tot = 0.0;
#pragma unroll
        for (int kk = 0; kk < K_; kk++) tot += g_loss[kk];
        if (out_size > 0) out[0] = (float)(tot / ((double)K_ * (double)TOTPOS));
#pragma unroll
        for (int kk = 0; kk < K_; kk++)
            if (1 + kk < out_size) out[1 + kk] = (float)(g_acc[kk] / (double)TOTPOS);
    }
}

// ---------------- launch: PDL pipeline G0,[L0,G1*],[L1,G2*],...,L11 ----------------
extern "C" void kernel_launch(void* const* d_in, const int* in_sizes, int n_in,
                              void* d_out, int out_size) {
    const float* z  = (const float*)d_in[0];
    const float* c  = (const float*)d_in[1];
    const float* W  = (const float*)d_in[2];
    const float* b  = (const float*)d_in[3];
    const int* bidx = (const int*)d_in[4];
    const int* sidx = (const int*)d_in[5];

    zero_accum<<<1, 32>>>();

    dim3 ggrid(9, SU);
    gemm_k<<<ggrid, 256>>>(c, W, b, 0);

    for (int k = 0; k < K_; k++) {
        loss_k<<<BLOCKS_PER_K, 256>>>(z, bidx, sidx, k);
        if (k + 1 < K_) {
            // G_{k+1} as PDL secondary: launches as soon as L_k's CTAs trigger,
            // overlapping the FMA-bound GEMM with the L2-bound loss. No data
            // hazard: G_{k+1} writes g_Wc[k+1], L_k reads g_Wc[k].
            cudaLaunchConfig_t cfg = {};
            cfg.gridDim = ggrid;
            cfg.blockDim = dim3(256, 1, 1);
            cfg.dynamicSmemBytes = 0;
            cfg.stream = 0;
            cudaLaunchAttribute at[1];
            at[0].id = cudaLaunchAttributeProgrammaticStreamSerialization;
            at[0].val.programmaticStreamSerializationAllowed = 1;
            cfg.attrs = at;
            cfg.numAttrs = 1;
            cudaLaunchKernelEx(&cfg, gemm_k, c, W, b, k + 1);
        }
    }

    finalize<<<1, 32>>>((float*)d_out, out_size);
}

// round 14
// speedup vs baseline: 1.1928x; 1.0629x over previous
#include <cuda_runtime.h>
#include <cstdint>

// Problem constants
#define S_    8
#define U_    8
#define K_    12
#define NEG_  17
#define ZD    64
#define CD    256
#define T_    1140
#define LEN   1128
#define SU    64
#define TOTPOS 72192

// ---------------- scratch ----------------
__device__ float  g_Wc[(size_t)K_ * TOTPOS * ZD];   // ~222 MB
__device__ double g_loss[K_];
__device__ double g_acc[K_];

__global__ void zero_accum() {
    int i = threadIdx.x;
    if (i < K_) { g_loss[i] = 0.0; g_acc[i] = 0.0; }
}

// ================= GEMM: BM=256 x BN=64, 8x8/thread, double-buffered =================
#define BM 256
#define BN 64
#define BK 16
#define ASB 260
#define BSB 68

__global__ __launch_bounds__(256, 2) void gemm_wc(const float* __restrict__ C,
                                                  const float* __restrict__ W,
                                                  const float* __restrict__ Bias) {
    __shared__ float As[2][BK][ASB];
    __shared__ float Bs[2][BK][BSB];

    const int k  = blockIdx.x;        // fastest: 12 k share the A tile via L2
    const int lt = blockIdx.y;        // 0..4 (5*256 = 1280 >= 1128)
    const int su = blockIdx.z;
    const int l0 = lt * BM;
    const int tid = threadIdx.x;
    const int ty = tid >> 3;          // 0..31 -> rows ty*8..+8
    const int tx = tid & 7;           // 0..7  -> cols tx*8..+8

    // load-index precompute
    const int brow = tid >> 2;        // B: 0..63
    const int bc4  = tid & 3;

    float4 aL[4]; float4 bL;

    // ---- chunk loader: A 256x16 (4 float4/thread), B 64x16 (1 float4/thread)
#define LOAD_CHUNK(kt) do {                                                     \
    _Pragma("unroll")                                                           \
    for (int r = 0; r < 4; r++) {                                               \
        int f = r * 256 + tid;                                                  \
        int row = f >> 2, c4 = f & 3;                                           \
        int rr = l0 + row; if (rr > T_ - 1) rr = T_ - 1;                        \
        aL[r] = *(const float4*)(C + ((size_t)su * T_ + rr) * CD + (kt) * BK + c4 * 4); \
    }                                                                           \
    bL = *(const float4*)(W + ((size_t)k * ZD + brow) * CD + (kt) * BK + bc4 * 4); \
} while (0)

#define STS_CHUNK(b) do {                                                       \
    _Pragma("unroll")                                                           \
    for (int r = 0; r < 4; r++) {                                               \
        int f = r * 256 + tid;                                                  \
        int row = f >> 2, c4 = f & 3;                                           \
        As[b][c4 * 4 + 0][row] = aL[r].x;                                       \
        As[b][c4 * 4 + 1][row] = aL[r].y;                                       \
        As[b][c4 * 4 + 2][row] = aL[r].z;                                       \
        As[b][c4 * 4 + 3][row] = aL[r].w;                                       \
    }                                                                           \
    Bs[b][bc4 * 4 + 0][brow] = bL.x;                                            \
    Bs[b][bc4 * 4 + 1][brow] = bL.y;                                            \
    Bs[b][bc4 * 4 + 2][brow] = bL.z;                                            \
    Bs[b][bc4 * 4 + 3][brow] = bL.w;                                            \
} while (0)

    LOAD_CHUNK(0);
    STS_CHUNK(0);
    __syncthreads();

    float acc[8][8];
#pragma unroll
    for (int i = 0; i < 8; i++)
#pragma unroll
        for (int j = 0; j < 8; j++) acc[i][j] = 0.0f;

    for (int kt = 0; kt < CD / BK; kt++) {
        if (kt < CD / BK - 1) LOAD_CHUNK(kt + 1);       // prefetch (latency hidden by compute)
        const int cb = kt & 1;
#pragma unroll
        for (int kk = 0; kk < BK; kk++) {
            float4 a0 = *(const float4*)&As[cb][kk][ty * 8];
            float4 a1 = *(const float4*)&As[cb][kk][ty * 8 + 4];
            float4 b0 = *(const float4*)&Bs[cb][kk][tx * 8];
            float4 b1 = *(const float4*)&Bs[cb][kk][tx * 8 + 4];
            float a[8] = {a0.x, a0.y, a0.z, a0.w, a1.x, a1.y, a1.z, a1.w};
            float b[8] = {b0.x, b0.y, b0.z, b0.w, b1.x, b1.y, b1.z, b1.w};
#pragma unroll
            for (int x = 0; x < 8; x++)
#pragma unroll
                for (int y = 0; y < 8; y++) acc[x][y] += a[x] * b[y];
        }
        if (kt < CD / BK - 1) STS_CHUNK((kt + 1) & 1);  // write other buffer
        __syncthreads();
    }

    // ---- epilogue: bias + store ----
    float bias[8];
#pragma unroll
    for (int j = 0; j < 8; j++) bias[j] = __ldg(Bias + k * ZD + tx * 8 + j);
    float* outp = g_Wc + ((size_t)k * TOTPOS + (size_t)su * LEN) * ZD;
#pragma unroll
    for (int i = 0; i < 8; i++) {
        const int l = l0 + ty * 8 + i;
        if (l < LEN) {
            float4 o0, o1;
            o0.x = acc[i][0] + bias[0]; o0.y = acc[i][1] + bias[1];
            o0.z = acc[i][2] + bias[2]; o0.w = acc[i][3] + bias[3];
            o1.x = acc[i][4] + bias[4]; o1.y = acc[i][5] + bias[5];
            o1.z = acc[i][6] + bias[6]; o1.w = acc[i][7] + bias[7];
            *(float4*)(outp + (size_t)l * ZD + tx * 8)     = o0;
            *(float4*)(outp + (size_t)l * ZD + tx * 8 + 4) = o1;
        }
    }
}

// ================= CPC loss (R2-proven, byte-identical math) =================
#define BLOCKS_PER_K 2256

__global__ __launch_bounds__(256) void cpc_loss(const float* __restrict__ z,
                                                const int* __restrict__ batch_index,
                                                const int* __restrict__ seq_index) {
    const int wid  = threadIdx.x >> 5;
    const int lane = threadIdx.x & 31;
    const int grp  = lane >> 3;
    const int lg   = lane & 7;

    const int k   = blockIdx.x / BLOCKS_PER_K;
    const int rem = blockIdx.x % BLOCKS_PER_K;
    const int wg  = rem * 8 + wid;
    const int su  = wg / 282;
    const int l   = (wg % 282) * 4 + grp;
    const int s   = su >> 3;
    const int u   = su & 7;
    const int kshift = k + 1;

    const float* wc = g_Wc + ((size_t)k * TOTPOS + (size_t)su * LEN + l) * ZD;
    const float4 wa = *(const float4*)(wc + 4 * lg);
    const float4 wb = *(const float4*)(wc + 32 + 4 * lg);

    const float* zp = z + ((size_t)(su * T_ + l + kshift)) * ZD;
    float4 za = *(const float4*)(zp + 4 * lg);
    float4 zb = *(const float4*)(zp + 32 + 4 * lg);
    float v = wa.x * za.x + wa.y * za.y + wa.z * za.z + wa.w * za.w
            + wb.x * zb.x + wb.y * zb.y + wb.z * zb.z + wb.w * zb.w;
    v += __shfl_xor_sync(0xffffffffu, v, 1);
    v += __shfl_xor_sync(0xffffffffu, v, 2);
    v += __shfl_xor_sync(0xffffffffu, v, 4);
    const float pos = v * 0.125f;

    const int* bip = batch_index + (k * U_ + u) * NEG_;
    const int* sip = seq_index + ((size_t)((k * S_ + s) * U_ + u) * NEG_) * LEN + l;
    int bis[NEG_], sis[NEG_];
#pragma unroll
    for (int n = 0; n < NEG_; n++) {
        bis[n] = __ldg(bip + n);
        sis[n] = __ldg(sip + (size_t)n * LEN);
    }

    float m = pos, ssum = 1.0f, ok = 1.0f;
#pragma unroll
    for (int n = 0; n < NEG_; n++) {
        const float* zr = z + ((size_t)((s * 8 + bis[n]) * T_ + sis[n] + kshift)) * ZD;
        float4 na = *(const float4*)(zr + 4 * lg);
        float4 nb = *(const float4*)(zr + 32 + 4 * lg);
        float d = wa.x * na.x + wa.y * na.y + wa.z * na.z + wa.w * na.w
                + wb.x * nb.x + wb.y * nb.y + wb.z * nb.z + wb.w * nb.w;
        d += __shfl_xor_sync(0xffffffffu, d, 1);
        d += __shfl_xor_sync(0xffffffffu, d, 2);
        d += __shfl_xor_sync(0xffffffffu, d, 4);
        d *= 0.125f;
        if (d > pos) ok = 0.0f;
        if (d > m) { ssum = ssum * __expf(m - d) + 1.0f; m = d; }
        else       { ssum += __expf(d - m); }
    }

    float lt = m + __logf(ssum) - pos;

    lt += __shfl_xor_sync(0xffffffffu, lt, 8);
    lt += __shfl_xor_sync(0xffffffffu, lt, 16);
    ok += __shfl_xor_sync(0xffffffffu, ok, 8);
    ok += __shfl_xor_sync(0xffffffffu, ok, 16);

    __shared__ float sL[8], sA[8];
    if (lane == 0) { sL[wid] = lt; sA[wid] = ok; }
    __syncthreads();
    if (threadIdx.x == 0) {
        float L = 0.f, A = 0.f;
#pragma unroll
        for (int i = 0; i < 8; i++) { L += sL[i]; A += sA[i]; }
        atomicAdd(&g_loss[k], (double)L);
        atomicAdd(&g_acc[k], (double)A);
    }
}

// ================= finalize =================
__global__ void finalize(float* __restrict__ out, int out_size) {
    if (threadIdx.x == 0) {
        double tot = 0.0;
#pragma unroll
        for (int kk = 0; kk < K_; kk++) tot += g_loss[kk];
        if (out_size > 0) out[0] = (float)(tot / ((double)K_ * (double)TOTPOS));
#pragma unroll
        for (int kk = 0; kk < K_; kk++)
            if (1 + kk < out_size) out[1 + kk] = (float)(g_acc[kk] / (double)TOTPOS);
    }
}

// ---------------- launch ----------------
extern "C" void kernel_launch(void* const* d_in, const int* in_sizes, int n_in,
                              void* d_out, int out_size) {
    const float* z  = (const float*)d_in[0];
    const float* c  = (const float*)d_in[1];
    const float* W  = (const float*)d_in[2];
    const float* b  = (const float*)d_in[3];
    const int* bidx = (const int*)d_in[4];
    const int* sidx = (const int*)d_in[5];

    zero_accum<<<1, 32>>>();

    dim3 ggrid(K_, 5, SU);           // k fastest -> A-tile L2 reuse across k
    gemm_wc<<<ggrid, 256>>>(c, W, b);

    cpc_loss<<<K_ * BLOCKS_PER_K, 256>>>(z, bidx, sidx);

    finalize<<<1, 32>>>((float*)d_out, out_size);
}